// round 1
// baseline (speedup 1.0000x reference)
#include <cuda_runtime.h>

// ---------------------------------------------------------------------------
// HapticNet: conv encoders (pressure/torque) -> concat(+fragility) -> proj
//            -> LSTM(64, T=256) -> head(4) with sigmoid.
// Output layout (flattened tuple): out[B*T*4] | hT[B*64] | cT[B*64]
// ---------------------------------------------------------------------------

#define DEVINL __device__ __forceinline__

constexpr int B = 64, T = 256, W = 20, NP = 6, NT = 12, CC = 32, FD = 8, PROJ = 64;
constexpr int L1c = 18;                 // conv1 output length (W - 2)
constexpr int NG = 4 * PROJ;            // 256 gates
constexpr int WPB = 8;                  // windows per block in encoder
constexpr int NWIN = B * T;             // 16384

// scratch: precomputed input-gate activations xg = feat @ Wih^T + (bih + bhh)
__device__ float g_xg[NWIN * NG];       // 16 MB

DEVINL void fma2(unsigned long long& d, unsigned long long a, unsigned long long b) {
    asm("fma.rn.f32x2 %0, %1, %2, %0;" : "+l"(d) : "l"(a), "l"(b));
}

DEVINL float sigm(float x) { return __fdividef(1.f, 1.f + __expf(-x)); }
DEVINL float tanh_(float x) { return __fdividef(2.f, 1.f + __expf(-2.f * x)) - 1.f; }

// ---------------------------------------------------------------------------
// conv1: (NCH, 20) -> relu -> (32, 18), weights in shared [o][i][k]
// ---------------------------------------------------------------------------
template <int NCH>
DEVINL void conv1(const float* __restrict__ s_x, const float* __restrict__ s_w1,
                  const float* __restrict__ s_b1, float* __restrict__ s_h1, int tid) {
    for (int idx = tid; idx < CC * L1c; idx += 256) {
        int o = idx & 31, l = idx >> 5;
        float acc = s_b1[o];
#pragma unroll
        for (int k = 0; k < 3; k++)
#pragma unroll
            for (int i = 0; i < NCH; i++)
                acc = fmaf(s_x[(l + k) * NCH + i], s_w1[(o * NCH + i) * 3 + k], acc);
        s_h1[o * L1c + l] = fmaxf(acc, 0.f);
    }
}

// ---------------------------------------------------------------------------
// conv2 + relu + mean-pool over 16 positions.
// weights in shared padded [o][c][4] (k0,k1,k2,0); h1 stored [c][18].
// thread (o = tid>>4, l = tid&15) computes channels o and o+16 at position l;
// mean via width-16 shuffle reduction.
// ---------------------------------------------------------------------------
DEVINL void conv2_mean(const float* __restrict__ s_h1, const float* __restrict__ s_w2,
                       const float* __restrict__ s_b2, float* __restrict__ s_cat_out, int tid) {
    int o = tid >> 4, l = tid & 15;
    float a0 = s_b2[o], a1 = s_b2[o + 16];
#pragma unroll
    for (int c = 0; c < CC; c++) {
        float4 w0 = *reinterpret_cast<const float4*>(s_w2 + (o * CC + c) * 4);
        float4 w1 = *reinterpret_cast<const float4*>(s_w2 + ((o + 16) * CC + c) * 4);
        float h0 = s_h1[c * L1c + l];
        float h1 = s_h1[c * L1c + l + 1];
        float h2 = s_h1[c * L1c + l + 2];
        a0 = fmaf(w0.x, h0, a0); a0 = fmaf(w0.y, h1, a0); a0 = fmaf(w0.z, h2, a0);
        a1 = fmaf(w1.x, h0, a1); a1 = fmaf(w1.y, h1, a1); a1 = fmaf(w1.z, h2, a1);
    }
    float r0 = fmaxf(a0, 0.f), r1 = fmaxf(a1, 0.f);
#pragma unroll
    for (int s = 8; s > 0; s >>= 1) {
        r0 += __shfl_down_sync(0xffffffffu, r0, s, 16);
        r1 += __shfl_down_sync(0xffffffffu, r1, s, 16);
    }
    if ((tid & 15) == 0) {
        s_cat_out[o]      = r0 * (1.f / 16.f);
        s_cat_out[o + 16] = r1 * (1.f / 16.f);
    }
}

// ---------------------------------------------------------------------------
// Encoder kernel: per window -> pf(32), tf(32), ff(8) -> proj(64,relu)
//                 -> xg(256) = feat @ Wih^T + bih + bhh   (to g_xg)
// ---------------------------------------------------------------------------
__global__ void __launch_bounds__(256) enc_kernel(
    const float* __restrict__ pressure, const float* __restrict__ torque,
    const float* __restrict__ frag,
    const float* __restrict__ pw1, const float* __restrict__ pb1,
    const float* __restrict__ pw2, const float* __restrict__ pb2,
    const float* __restrict__ tw1, const float* __restrict__ tb1,
    const float* __restrict__ tw2, const float* __restrict__ tb2,
    const float* __restrict__ fw, const float* __restrict__ fb,
    const float* __restrict__ prw, const float* __restrict__ prb,
    const float* __restrict__ Wih, const float* __restrict__ bih,
    const float* __restrict__ bhh) {
    __shared__ __align__(16) float s_pw1[CC * NP * 3];
    __shared__ __align__(16) float s_tw1[CC * NT * 3];
    __shared__ __align__(16) float s_pw2[CC * CC * 4];
    __shared__ __align__(16) float s_tw2[CC * CC * 4];
    __shared__ float s_pb1[CC], s_pb2[CC], s_tb1[CC], s_tb2[CC];
    __shared__ __align__(16) float s_x[W * NT];
    __shared__ __align__(16) float s_h1[CC * L1c];
    __shared__ __align__(16) float s_cat[2 * CC + FD];
    __shared__ __align__(16) float s_feat[PROJ];

    const int tid = threadIdx.x;

    // stage weights (conv stages only; proj/Wih read from global, L1-hot)
    for (int i = tid; i < CC * NP * 3; i += 256) s_pw1[i] = pw1[i];
    for (int i = tid; i < CC * NT * 3; i += 256) s_tw1[i] = tw1[i];
    for (int i = tid; i < CC * CC; i += 256) {
        s_pw2[i * 4 + 0] = pw2[i * 3 + 0];
        s_pw2[i * 4 + 1] = pw2[i * 3 + 1];
        s_pw2[i * 4 + 2] = pw2[i * 3 + 2];
        s_pw2[i * 4 + 3] = 0.f;
        s_tw2[i * 4 + 0] = tw2[i * 3 + 0];
        s_tw2[i * 4 + 1] = tw2[i * 3 + 1];
        s_tw2[i * 4 + 2] = tw2[i * 3 + 2];
        s_tw2[i * 4 + 3] = 0.f;
    }
    if (tid < CC) {
        s_pb1[tid] = pb1[tid]; s_pb2[tid] = pb2[tid];
        s_tb1[tid] = tb1[tid]; s_tb2[tid] = tb2[tid];
    }
    __syncthreads();

    for (int w = 0; w < WPB; ++w) {
        const int wi = blockIdx.x * WPB + w;
        const int b = wi >> 8;  // T == 256

        // ---- pressure encoder ----
        for (int i = tid; i < W * NP; i += 256) s_x[i] = pressure[wi * (W * NP) + i];
        __syncthreads();
        conv1<NP>(s_x, s_pw1, s_pb1, s_h1, tid);
        __syncthreads();
        conv2_mean(s_h1, s_pw2, s_pb2, s_cat, tid);
        __syncthreads();

        // ---- torque encoder ----
        for (int i = tid; i < W * NT; i += 256) s_x[i] = torque[wi * (W * NT) + i];
        __syncthreads();
        conv1<NT>(s_x, s_tw1, s_tb1, s_h1, tid);
        __syncthreads();
        conv2_mean(s_h1, s_tw2, s_tb2, s_cat + CC, tid);

        // ---- fragility features ----
        if (tid < FD) s_cat[2 * CC + tid] = fmaxf(fmaf(frag[b], fw[tid], fb[tid]), 0.f);
        __syncthreads();

        // ---- projection (64 x 72, relu) ----
        if (tid < PROJ) {
            float acc = prb[tid];
            const float* pr = prw + tid * (2 * CC + FD);
#pragma unroll
            for (int j = 0; j < 2 * CC + FD; j += 4) {
                float4 wv = *reinterpret_cast<const float4*>(pr + j);
                acc = fmaf(wv.x, s_cat[j], acc);
                acc = fmaf(wv.y, s_cat[j + 1], acc);
                acc = fmaf(wv.z, s_cat[j + 2], acc);
                acc = fmaf(wv.w, s_cat[j + 3], acc);
            }
            s_feat[tid] = fmaxf(acc, 0.f);
        }
        __syncthreads();

        // ---- xg = feat @ Wih^T + bih + bhh  (one gate per thread) ----
        {
            float acc = bih[tid] + bhh[tid];
            const float4* wr = reinterpret_cast<const float4*>(Wih + tid * PROJ);
            const float4* f4 = reinterpret_cast<const float4*>(s_feat);
#pragma unroll
            for (int q = 0; q < PROJ / 4; q++) {
                float4 wv = wr[q];
                float4 fv = f4[q];
                acc = fmaf(wv.x, fv.x, acc);
                acc = fmaf(wv.y, fv.y, acc);
                acc = fmaf(wv.z, fv.z, acc);
                acc = fmaf(wv.w, fv.w, acc);
            }
            g_xg[wi * NG + tid] = acc;
        }
        __syncthreads();
    }
}

// ---------------------------------------------------------------------------
// LSTM kernel: one block per batch row. 256 threads = one gate each.
// Whh row in registers (f32x2 pairs), h in shared. Head fused per step.
// ---------------------------------------------------------------------------
__global__ void __launch_bounds__(256) lstm_kernel(
    const float* __restrict__ Whh, const float* __restrict__ hw,
    const float* __restrict__ hb, float* __restrict__ out) {
    __shared__ __align__(16) float s_h[PROJ];
    __shared__ float s_gates[NG];
    __shared__ __align__(16) float s_hw[4 * PROJ];
    __shared__ float s_hb[4];

    const int tid = threadIdx.x;
    const int b = blockIdx.x;

    // Whh row for this gate, packed as f32x2 pairs (even/odd j)
    unsigned long long wreg[PROJ / 2];
    {
        const ulonglong2* w2 = reinterpret_cast<const ulonglong2*>(Whh + tid * PROJ);
#pragma unroll
        for (int q = 0; q < PROJ / 4; q++) {
            ulonglong2 v = w2[q];
            wreg[2 * q] = v.x;
            wreg[2 * q + 1] = v.y;
        }
    }

    if (tid < PROJ) s_h[tid] = 0.f;
    s_hw[tid] = hw[tid];
    if (tid < 4) s_hb[tid] = hb[tid];
    float c = 0.f;

    const float* xg = g_xg + b * T * NG;
    float xnext = xg[tid];
    __syncthreads();

    for (int t = 0; t < T; t++) {
        float xcur = xnext;
        int tn = (t + 1 < T) ? (t + 1) : (T - 1);
        xnext = xg[tn * NG + tid];  // prefetch next step

        // gate pre-activation: xg + Whh[g] . h   (packed f32x2 dot)
        unsigned long long acc;
        asm("mov.b64 %0, {%1,%2};" : "=l"(acc) : "f"(xcur), "f"(0.f));
        const ulonglong2* h2 = reinterpret_cast<const ulonglong2*>(s_h);
#pragma unroll
        for (int q = 0; q < PROJ / 4; q++) {
            ulonglong2 hv = h2[q];
            fma2(acc, wreg[2 * q], hv.x);
            fma2(acc, wreg[2 * q + 1], hv.y);
        }
        float lo, hi;
        asm("mov.b64 {%0,%1}, %2;" : "=f"(lo), "=f"(hi) : "l"(acc));
        s_gates[tid] = lo + hi;
        __syncthreads();

        if (tid < PROJ) {
            float gi = s_gates[tid];
            float gf = s_gates[PROJ + tid];
            float gg = s_gates[2 * PROJ + tid];
            float go = s_gates[3 * PROJ + tid];
            c = sigm(gf) * c + sigm(gi) * tanh_(gg);
            s_h[tid] = sigm(go) * tanh_(c);
        }
        __syncthreads();

        // fused head: out[b,t,m] = sigmoid(h . hw[m] + hb[m])
        if (tid >= 64 && tid < 68) {
            int m = tid - 64;
            float acc2 = s_hb[m];
            const float* hwr = s_hw + m * PROJ;
#pragma unroll
            for (int j = 0; j < PROJ; j++) acc2 = fmaf(hwr[j], s_h[j], acc2);
            out[(b * T + t) * 4 + m] = sigm(acc2);
        }
    }

    if (tid < PROJ) {
        out[B * T * 4 + b * PROJ + tid] = s_h[tid];              // hT
        out[B * T * 4 + B * PROJ + b * PROJ + tid] = c;          // cT
    }
}

// ---------------------------------------------------------------------------
extern "C" void kernel_launch(void* const* d_in, const int* in_sizes, int n_in,
                              void* d_out, int out_size) {
    const float* pressure = (const float*)d_in[0];
    const float* torque   = (const float*)d_in[1];
    const float* frag     = (const float*)d_in[2];
    const float* pw1 = (const float*)d_in[3];
    const float* pb1 = (const float*)d_in[4];
    const float* pw2 = (const float*)d_in[5];
    const float* pb2 = (const float*)d_in[6];
    const float* tw1 = (const float*)d_in[7];
    const float* tb1 = (const float*)d_in[8];
    const float* tw2 = (const float*)d_in[9];
    const float* tb2 = (const float*)d_in[10];
    const float* fw  = (const float*)d_in[11];
    const float* fb  = (const float*)d_in[12];
    const float* prw = (const float*)d_in[13];
    const float* prb = (const float*)d_in[14];
    const float* Wih = (const float*)d_in[15];
    const float* Whh = (const float*)d_in[16];
    const float* bih = (const float*)d_in[17];
    const float* bhh = (const float*)d_in[18];
    const float* hw  = (const float*)d_in[19];
    const float* hb  = (const float*)d_in[20];

    enc_kernel<<<NWIN / WPB, 256>>>(pressure, torque, frag,
                                    pw1, pb1, pw2, pb2, tw1, tb1, tw2, tb2,
                                    fw, fb, prw, prb, Wih, bih, bhh);
    lstm_kernel<<<B, 256>>>(Whh, hw, hb, (float*)d_out);
}